// round 1
// baseline (speedup 1.0000x reference)
#include <cuda_runtime.h>
#include <cuda_bf16.h>

#define NNODES 100000
#define NEDGES 1600000
#define INF    128
#define HF     64     // HEADS*OUT_FEATS
#define NEG_SLOPE 0.2f
#define EPS_F  1e-16f

// ---------------- static device scratch (no allocations allowed) ----------
__device__ float  g_h[NNODES * HF];          // 25.6 MB  projected features
__device__ float4 g_el[NNODES];              // [N][4] left scores
__device__ float4 g_er[NNODES];              // [N][4] right scores
__device__ float  g_expS[NEDGES * 4];        // 25.6 MB per-edge exp scores
__device__ float  g_denom[NNODES * 4];       // softmax denominators
__device__ int    g_counts[NNODES];
__device__ int    g_cursor[NNODES];
__device__ int    g_rowptr[NNODES + 1];
__device__ int    g_perm[NEDGES];            // edge ids grouped by target

// ---------------- zero scratch that accumulates ---------------------------
__global__ void zero_kernel() {
    int i = blockIdx.x * blockDim.x + threadIdx.x;
    int stride = gridDim.x * blockDim.x;
    for (int j = i; j < NNODES * 4; j += stride) g_denom[j] = 0.0f;
    for (int j = i; j < NNODES; j += stride)     g_counts[j] = 0;
}

// ---------------- K1: h = feat @ W, fused el/er epilogue ------------------
__device__ __forceinline__ void kstep(float a, const float4* __restrict__ wr,
                                      float4* acc) {
#pragma unroll
    for (int jj = 0; jj < 16; jj++) {
        float4 w = wr[jj];
        acc[jj].x = fmaf(a, w.x, acc[jj].x);
        acc[jj].y = fmaf(a, w.y, acc[jj].y);
        acc[jj].z = fmaf(a, w.z, acc[jj].z);
        acc[jj].w = fmaf(a, w.w, acc[jj].w);
    }
}

__global__ __launch_bounds__(256) void gemm_kernel(
    const float* __restrict__ feat, const float* __restrict__ W,
    const float* __restrict__ attL, const float* __restrict__ attR) {
    __shared__ float sW[INF * HF];
    __shared__ float sAL[HF], sAR[HF];
    for (int i = threadIdx.x; i < INF * HF; i += 256) sW[i] = W[i];
    if (threadIdx.x < HF) {
        sAL[threadIdx.x] = attL[threadIdx.x];
        sAR[threadIdx.x] = attR[threadIdx.x];
    }
    __syncthreads();

    int node = blockIdx.x * 256 + threadIdx.x;
    if (node >= NNODES) return;

    float4 acc[16];
#pragma unroll
    for (int j = 0; j < 16; j++) acc[j] = make_float4(0.f, 0.f, 0.f, 0.f);

    const float4* f4 = reinterpret_cast<const float4*>(feat + (size_t)node * INF);
    const float4* w4 = reinterpret_cast<const float4*>(sW);

#pragma unroll 2
    for (int k0 = 0; k0 < 32; k0++) {
        float4 fv = f4[k0];
        const float4* w0 = w4 + (k0 * 4) * 16;
        kstep(fv.x, w0 + 0 * 16, acc);
        kstep(fv.y, w0 + 1 * 16, acc);
        kstep(fv.z, w0 + 2 * 16, acc);
        kstep(fv.w, w0 + 3 * 16, acc);
    }

    float4* h4 = reinterpret_cast<float4*>(g_h + (size_t)node * HF);
    float el[4] = {0.f, 0.f, 0.f, 0.f};
    float er[4] = {0.f, 0.f, 0.f, 0.f};
#pragma unroll
    for (int jj = 0; jj < 16; jj++) {
        h4[jj] = acc[jj];
        int hd = jj >> 2;               // 4 consecutive float4 per head
        int j0 = jj * 4;
        el[hd] += acc[jj].x * sAL[j0] + acc[jj].y * sAL[j0 + 1] +
                  acc[jj].z * sAL[j0 + 2] + acc[jj].w * sAL[j0 + 3];
        er[hd] += acc[jj].x * sAR[j0] + acc[jj].y * sAR[j0 + 1] +
                  acc[jj].z * sAR[j0 + 2] + acc[jj].w * sAR[j0 + 3];
    }
    g_el[node] = make_float4(el[0], el[1], el[2], el[3]);
    g_er[node] = make_float4(er[0], er[1], er[2], er[3]);
}

// ---------------- K2: per-edge exp scores + denom + histogram -------------
// Note: the reference's global-max shift cancels in e/(sum e + EPS) up to
// ~1e-14 relative (EPS is dwarfed by denom >= exp(-~8)); we skip it.
__global__ void edge_kernel(const int* __restrict__ src,
                            const int* __restrict__ trg) {
    int e = blockIdx.x * blockDim.x + threadIdx.x;
    if (e >= NEDGES) return;
    int s = src[e], t = trg[e];
    float4 l = g_el[s];
    float4 r = g_er[t];
    float sx = l.x + r.x, sy = l.y + r.y, sz = l.z + r.z, sw = l.w + r.w;
    sx = sx > 0.f ? sx : NEG_SLOPE * sx;
    sy = sy > 0.f ? sy : NEG_SLOPE * sy;
    sz = sz > 0.f ? sz : NEG_SLOPE * sz;
    sw = sw > 0.f ? sw : NEG_SLOPE * sw;
    float ex = __expf(sx), ey = __expf(sy), ez = __expf(sz), ew = __expf(sw);
    reinterpret_cast<float4*>(g_expS)[e] = make_float4(ex, ey, ez, ew);
    atomicAdd(&g_denom[t * 4 + 0], ex);
    atomicAdd(&g_denom[t * 4 + 1], ey);
    atomicAdd(&g_denom[t * 4 + 2], ez);
    atomicAdd(&g_denom[t * 4 + 3], ew);
    atomicAdd(&g_counts[t], 1);
}

// ---------------- K3: single-block exclusive scan of counts ---------------
#define SCAN_T 1024
#define CHUNK  98          // 1024*98 = 100352 >= NNODES
__global__ __launch_bounds__(SCAN_T) void scan_kernel() {
    int tid = threadIdx.x;
    int base = tid * CHUNK;
    int sum = 0;
    for (int i = 0; i < CHUNK; i++) {
        int idx = base + i;
        if (idx < NNODES) sum += g_counts[idx];
    }
    __shared__ int sh[SCAN_T];
    sh[tid] = sum;
    __syncthreads();
    for (int off = 1; off < SCAN_T; off <<= 1) {
        int v = (tid >= off) ? sh[tid - off] : 0;
        __syncthreads();
        sh[tid] += v;
        __syncthreads();
    }
    int run = sh[tid] - sum;   // exclusive prefix of this chunk
    for (int i = 0; i < CHUNK; i++) {
        int idx = base + i;
        if (idx < NNODES) {
            g_rowptr[idx] = run;
            g_cursor[idx] = run;
            run += g_counts[idx];
        }
    }
    if (tid == 0) g_rowptr[NNODES] = NEDGES;
}

// ---------------- K4: scatter edge ids grouped by target ------------------
__global__ void scatter_kernel(const int* __restrict__ trg) {
    int e = blockIdx.x * blockDim.x + threadIdx.x;
    if (e >= NEDGES) return;
    int t = trg[e];
    int pos = atomicAdd(&g_cursor[t], 1);
    g_perm[pos] = e;
}

// ---------------- K5: warp-per-node weighted aggregation ------------------
__global__ __launch_bounds__(256) void agg_kernel(const int* __restrict__ src,
                                                  float* __restrict__ out) {
    int gw = (blockIdx.x * 256 + threadIdx.x) >> 5;
    int lane = threadIdx.x & 31;
    if (gw >= NNODES) return;
    int n = gw;
    int beg = g_rowptr[n];
    int end = g_rowptr[n + 1];
    int head = lane >> 3;                      // feature pair 2*lane -> head
    float rd = 1.0f / (g_denom[n * 4 + head] + EPS_F);
    float ax = 0.f, ay = 0.f;
    const float2* h2 = reinterpret_cast<const float2*>(g_h);
    for (int i = beg; i < end; i++) {
        int e = g_perm[i];                     // uniform -> broadcast load
        int s = src[e];
        float a = g_expS[e * 4 + head] * rd;
        float2 hv = h2[(size_t)s * 32 + lane]; // coalesced 256B row
        ax = fmaf(hv.x, a, ax);
        ay = fmaf(hv.y, a, ay);
    }
    reinterpret_cast<float2*>(out)[(size_t)n * 32 + lane] = make_float2(ax, ay);
}

// ---------------- launch ---------------------------------------------------
extern "C" void kernel_launch(void* const* d_in, const int* in_sizes, int n_in,
                              void* d_out, int out_size) {
    const float* feat = (const float*)d_in[0];
    const float* W    = (const float*)d_in[1];
    const float* attL = (const float*)d_in[2];
    const float* attR = (const float*)d_in[3];
    const int*   src  = (const int*)d_in[4];
    const int*   trg  = (const int*)d_in[5];
    float* out = (float*)d_out;

    zero_kernel<<<256, 256>>>();
    gemm_kernel<<<(NNODES + 255) / 256, 256>>>(feat, W, attL, attR);
    edge_kernel<<<(NEDGES + 255) / 256, 256>>>(src, trg);
    scan_kernel<<<1, SCAN_T>>>();
    scatter_kernel<<<(NEDGES + 255) / 256, 256>>>(trg);
    agg_kernel<<<(NNODES * 32 + 255) / 256, 256>>>(src, out);
}

// round 2
// speedup vs baseline: 1.6859x; 1.6859x over previous
#include <cuda_runtime.h>
#include <cuda_bf16.h>

#define NNODES 100000
#define NEDGES 1600000
#define INF    128
#define HF     64     // HEADS*OUT_FEATS
#define NEG_SLOPE 0.2f
#define EPS_F  1e-16f

#define SBLK 256
#define NSB  ((NNODES + SBLK - 1) / SBLK)   // 391 scan blocks

// ---------------- static device scratch (no allocations allowed) ----------
__device__ float  g_h[NNODES * HF];          // 25.6 MB  projected features
__device__ float4 g_el[NNODES];              // [N][4] left scores
__device__ float4 g_er[NNODES];              // [N][4] right scores
__device__ float  g_expS[NEDGES * 4];        // 25.6 MB per-edge exp scores
__device__ float  g_denom[NNODES * 4];       // softmax denominators
__device__ int    g_counts[NNODES];
__device__ int    g_cursor[NNODES];
__device__ int    g_rowptr[NNODES + 1];
__device__ int    g_perm[NEDGES];            // edge ids grouped by target
__device__ int    g_bsum[NSB];               // per-block count sums
__device__ int    g_boff[NSB];               // exclusive scan of g_bsum

// ---------------- zero scratch that accumulates ---------------------------
__global__ void zero_kernel() {
    int i = blockIdx.x * blockDim.x + threadIdx.x;
    int stride = gridDim.x * blockDim.x;
    for (int j = i; j < NNODES * 4; j += stride) g_denom[j] = 0.0f;
    for (int j = i; j < NNODES; j += stride)     g_counts[j] = 0;
}

// ---------------- K1: h = feat @ W, fused el/er epilogue ------------------
__device__ __forceinline__ void kstep(float a, const float4* __restrict__ wr,
                                      float4* acc) {
#pragma unroll
    for (int jj = 0; jj < 16; jj++) {
        float4 w = wr[jj];
        acc[jj].x = fmaf(a, w.x, acc[jj].x);
        acc[jj].y = fmaf(a, w.y, acc[jj].y);
        acc[jj].z = fmaf(a, w.z, acc[jj].z);
        acc[jj].w = fmaf(a, w.w, acc[jj].w);
    }
}

__global__ __launch_bounds__(256) void gemm_kernel(
    const float* __restrict__ feat, const float* __restrict__ W,
    const float* __restrict__ attL, const float* __restrict__ attR) {
    __shared__ float sW[INF * HF];
    __shared__ float sAL[HF], sAR[HF];
    for (int i = threadIdx.x; i < INF * HF; i += 256) sW[i] = W[i];
    if (threadIdx.x < HF) {
        sAL[threadIdx.x] = attL[threadIdx.x];
        sAR[threadIdx.x] = attR[threadIdx.x];
    }
    __syncthreads();

    int node = blockIdx.x * 256 + threadIdx.x;
    if (node >= NNODES) return;

    float4 acc[16];
#pragma unroll
    for (int j = 0; j < 16; j++) acc[j] = make_float4(0.f, 0.f, 0.f, 0.f);

    const float4* f4 = reinterpret_cast<const float4*>(feat + (size_t)node * INF);
    const float4* w4 = reinterpret_cast<const float4*>(sW);

#pragma unroll 2
    for (int k0 = 0; k0 < 32; k0++) {
        float4 fv = f4[k0];
        const float4* w0 = w4 + (k0 * 4) * 16;
        kstep(fv.x, w0 + 0 * 16, acc);
        kstep(fv.y, w0 + 1 * 16, acc);
        kstep(fv.z, w0 + 2 * 16, acc);
        kstep(fv.w, w0 + 3 * 16, acc);
    }

    float4* h4 = reinterpret_cast<float4*>(g_h + (size_t)node * HF);
    float el[4] = {0.f, 0.f, 0.f, 0.f};
    float er[4] = {0.f, 0.f, 0.f, 0.f};
#pragma unroll
    for (int jj = 0; jj < 16; jj++) {
        h4[jj] = acc[jj];
        int hd = jj >> 2;               // 4 consecutive float4 per head
        int j0 = jj * 4;
        el[hd] += acc[jj].x * sAL[j0] + acc[jj].y * sAL[j0 + 1] +
                  acc[jj].z * sAL[j0 + 2] + acc[jj].w * sAL[j0 + 3];
        er[hd] += acc[jj].x * sAR[j0] + acc[jj].y * sAR[j0 + 1] +
                  acc[jj].z * sAR[j0 + 2] + acc[jj].w * sAR[j0 + 3];
    }
    g_el[node] = make_float4(el[0], el[1], el[2], el[3]);
    g_er[node] = make_float4(er[0], er[1], er[2], er[3]);
}

// ---------------- K2: per-edge exp scores + denom + histogram -------------
// Note: the reference's global-max shift cancels in e/(sum e + EPS) up to
// ~1e-14 relative (EPS is dwarfed by denom >= exp(-~8)); we skip it.
__global__ void edge_kernel(const int* __restrict__ src,
                            const int* __restrict__ trg) {
    int e = blockIdx.x * blockDim.x + threadIdx.x;
    if (e >= NEDGES) return;
    int s = __ldg(&src[e]), t = __ldg(&trg[e]);
    float4 l = g_el[s];
    float4 r = g_er[t];
    float sx = l.x + r.x, sy = l.y + r.y, sz = l.z + r.z, sw = l.w + r.w;
    sx = sx > 0.f ? sx : NEG_SLOPE * sx;
    sy = sy > 0.f ? sy : NEG_SLOPE * sy;
    sz = sz > 0.f ? sz : NEG_SLOPE * sz;
    sw = sw > 0.f ? sw : NEG_SLOPE * sw;
    float ex = __expf(sx), ey = __expf(sy), ez = __expf(sz), ew = __expf(sw);
    reinterpret_cast<float4*>(g_expS)[e] = make_float4(ex, ey, ez, ew);
    atomicAdd(&g_denom[t * 4 + 0], ex);
    atomicAdd(&g_denom[t * 4 + 1], ey);
    atomicAdd(&g_denom[t * 4 + 2], ez);
    atomicAdd(&g_denom[t * 4 + 3], ew);
    atomicAdd(&g_counts[t], 1);
}

// ---------------- K3: 3-phase parallel exclusive scan of counts -----------
// Phase A: per-block (256 elems) sums.
__global__ __launch_bounds__(SBLK) void scan1_kernel() {
    int i = blockIdx.x * SBLK + threadIdx.x;
    int v = (i < NNODES) ? g_counts[i] : 0;
    // warp reduce
#pragma unroll
    for (int off = 16; off > 0; off >>= 1)
        v += __shfl_down_sync(0xFFFFFFFFu, v, off);
    __shared__ int ws[8];
    if ((threadIdx.x & 31) == 0) ws[threadIdx.x >> 5] = v;
    __syncthreads();
    if (threadIdx.x < 8) {
        int s = ws[threadIdx.x];
#pragma unroll
        for (int off = 4; off > 0; off >>= 1)
            s += __shfl_down_sync(0xFFu, s, off);
        if (threadIdx.x == 0) g_bsum[blockIdx.x] = s;
    }
}

// Phase B: single small block scans NSB block sums (exclusive).
__global__ __launch_bounds__(512) void scan2_kernel() {
    __shared__ int sh[512];
    int tid = threadIdx.x;
    int v = (tid < NSB) ? g_bsum[tid] : 0;
    sh[tid] = v;
    __syncthreads();
#pragma unroll
    for (int off = 1; off < 512; off <<= 1) {
        int u = (tid >= off) ? sh[tid - off] : 0;
        __syncthreads();
        sh[tid] += u;
        __syncthreads();
    }
    if (tid < NSB) g_boff[tid] = sh[tid] - v;  // exclusive
}

// Phase C: block-local exclusive scan + global offset -> rowptr/cursor.
__global__ __launch_bounds__(SBLK) void scan3_kernel() {
    __shared__ int sh[SBLK];
    int tid = threadIdx.x;
    int i = blockIdx.x * SBLK + tid;
    int v = (i < NNODES) ? g_counts[i] : 0;
    sh[tid] = v;
    __syncthreads();
#pragma unroll
    for (int off = 1; off < SBLK; off <<= 1) {
        int u = (tid >= off) ? sh[tid - off] : 0;
        __syncthreads();
        sh[tid] += u;
        __syncthreads();
    }
    if (i < NNODES) {
        int pos = g_boff[blockIdx.x] + sh[tid] - v;  // exclusive prefix
        g_rowptr[i] = pos;
        g_cursor[i] = pos;
        if (i == NNODES - 1) g_rowptr[NNODES] = NEDGES;
    }
}

// ---------------- K4: scatter edge ids grouped by target ------------------
__global__ void scatter_kernel(const int* __restrict__ trg) {
    int e = blockIdx.x * blockDim.x + threadIdx.x;
    if (e >= NEDGES) return;
    int t = __ldg(&trg[e]);
    int pos = atomicAdd(&g_cursor[t], 1);
    g_perm[pos] = e;
}

// ---------------- K5: warp-per-node weighted aggregation ------------------
__global__ __launch_bounds__(256) void agg_kernel(const int* __restrict__ src,
                                                  float* __restrict__ out) {
    int gw = (blockIdx.x * 256 + threadIdx.x) >> 5;
    int lane = threadIdx.x & 31;
    if (gw >= NNODES) return;
    int n = gw;
    int beg = g_rowptr[n];
    int end = g_rowptr[n + 1];
    int head = lane >> 3;                      // feature pair 2*lane -> head
    float rd = 1.0f / (g_denom[n * 4 + head] + EPS_F);
    float ax = 0.f, ay = 0.f;
    const float2* h2 = reinterpret_cast<const float2*>(g_h);
    for (int i = beg; i < end; i++) {
        int e = __ldg(&g_perm[i]);             // uniform -> broadcast load
        int s = __ldg(&src[e]);
        float a = __ldg(&g_expS[e * 4 + head]) * rd;
        float2 hv = h2[(size_t)s * 32 + lane]; // coalesced 256B row
        ax = fmaf(hv.x, a, ax);
        ay = fmaf(hv.y, a, ay);
    }
    reinterpret_cast<float2*>(out)[(size_t)n * 32 + lane] = make_float2(ax, ay);
}

// ---------------- launch ---------------------------------------------------
extern "C" void kernel_launch(void* const* d_in, const int* in_sizes, int n_in,
                              void* d_out, int out_size) {
    const float* feat = (const float*)d_in[0];
    const float* W    = (const float*)d_in[1];
    const float* attL = (const float*)d_in[2];
    const float* attR = (const float*)d_in[3];
    const int*   src  = (const int*)d_in[4];
    const int*   trg  = (const int*)d_in[5];
    float* out = (float*)d_out;

    zero_kernel<<<256, 256>>>();
    gemm_kernel<<<(NNODES + 255) / 256, 256>>>(feat, W, attL, attR);
    edge_kernel<<<(NEDGES + 255) / 256, 256>>>(src, trg);
    scan1_kernel<<<NSB, SBLK>>>();
    scan2_kernel<<<1, 512>>>();
    scan3_kernel<<<NSB, SBLK>>>();
    scatter_kernel<<<(NEDGES + 255) / 256, 256>>>(trg);
    agg_kernel<<<(NNODES * 32 + 255) / 256, 256>>>(src, out);
}

// round 3
// speedup vs baseline: 1.9755x; 1.1718x over previous
#include <cuda_runtime.h>
#include <cuda_bf16.h>

#define NNODES 100000
#define NEDGES 1600000
#define INF    128
#define HF     64     // HEADS*OUT_FEATS
#define NEG_SLOPE 0.2f
#define EPS_F  1e-16f

#define SBLK 256
#define NSB  ((NNODES + SBLK - 1) / SBLK)   // 391 scan blocks

// ---------------- static device scratch (no allocations allowed) ----------
__device__ float  g_h[NNODES * HF];          // 25.6 MB  projected features
__device__ float4 g_el[NNODES];              // [N][4] left scores
__device__ float4 g_er[NNODES];              // [N][4] right scores
__device__ int    g_counts[NNODES];
__device__ int    g_cursor[NNODES];
__device__ int    g_rowptr[NNODES + 1];
__device__ int    g_psrc[NEDGES];            // src ids grouped by target
__device__ int    g_bsum[NSB];               // per-block count sums
__device__ int    g_boff[NSB];               // exclusive scan of g_bsum

// ---------------- zero counts ---------------------------------------------
__global__ void zero_kernel() {
    int i = blockIdx.x * blockDim.x + threadIdx.x;
    int stride = gridDim.x * blockDim.x;
    for (int j = i; j < NNODES; j += stride) g_counts[j] = 0;
}

// ---------------- K1: h = feat @ W, fused el/er epilogue ------------------
__device__ __forceinline__ void kstep(float a, const float4* __restrict__ wr,
                                      float4* acc) {
#pragma unroll
    for (int jj = 0; jj < 16; jj++) {
        float4 w = wr[jj];
        acc[jj].x = fmaf(a, w.x, acc[jj].x);
        acc[jj].y = fmaf(a, w.y, acc[jj].y);
        acc[jj].z = fmaf(a, w.z, acc[jj].z);
        acc[jj].w = fmaf(a, w.w, acc[jj].w);
    }
}

__global__ __launch_bounds__(256) void gemm_kernel(
    const float* __restrict__ feat, const float* __restrict__ W,
    const float* __restrict__ attL, const float* __restrict__ attR) {
    __shared__ float sW[INF * HF];
    __shared__ float sAL[HF], sAR[HF];
    for (int i = threadIdx.x; i < INF * HF; i += 256) sW[i] = W[i];
    if (threadIdx.x < HF) {
        sAL[threadIdx.x] = attL[threadIdx.x];
        sAR[threadIdx.x] = attR[threadIdx.x];
    }
    __syncthreads();

    int node = blockIdx.x * 256 + threadIdx.x;
    if (node >= NNODES) return;

    float4 acc[16];
#pragma unroll
    for (int j = 0; j < 16; j++) acc[j] = make_float4(0.f, 0.f, 0.f, 0.f);

    const float4* f4 = reinterpret_cast<const float4*>(feat + (size_t)node * INF);
    const float4* w4 = reinterpret_cast<const float4*>(sW);

#pragma unroll 2
    for (int k0 = 0; k0 < 32; k0++) {
        float4 fv = f4[k0];
        const float4* w0 = w4 + (k0 * 4) * 16;
        kstep(fv.x, w0 + 0 * 16, acc);
        kstep(fv.y, w0 + 1 * 16, acc);
        kstep(fv.z, w0 + 2 * 16, acc);
        kstep(fv.w, w0 + 3 * 16, acc);
    }

    float4* h4 = reinterpret_cast<float4*>(g_h + (size_t)node * HF);
    float el[4] = {0.f, 0.f, 0.f, 0.f};
    float er[4] = {0.f, 0.f, 0.f, 0.f};
#pragma unroll
    for (int jj = 0; jj < 16; jj++) {
        h4[jj] = acc[jj];
        int hd = jj >> 2;               // 4 consecutive float4 per head
        int j0 = jj * 4;
        el[hd] += acc[jj].x * sAL[j0] + acc[jj].y * sAL[j0 + 1] +
                  acc[jj].z * sAL[j0 + 2] + acc[jj].w * sAL[j0 + 3];
        er[hd] += acc[jj].x * sAR[j0] + acc[jj].y * sAR[j0 + 1] +
                  acc[jj].z * sAR[j0 + 2] + acc[jj].w * sAR[j0 + 3];
    }
    g_el[node] = make_float4(el[0], el[1], el[2], el[3]);
    g_er[node] = make_float4(er[0], er[1], er[2], er[3]);
}

// ---------------- K2: target-degree histogram -----------------------------
__global__ void count_kernel(const int* __restrict__ trg) {
    int e = blockIdx.x * blockDim.x + threadIdx.x;
    if (e >= NEDGES) return;
    atomicAdd(&g_counts[__ldg(&trg[e])], 1);
}

// ---------------- K3: 3-phase parallel exclusive scan of counts -----------
__global__ __launch_bounds__(SBLK) void scan1_kernel() {
    int i = blockIdx.x * SBLK + threadIdx.x;
    int v = (i < NNODES) ? g_counts[i] : 0;
#pragma unroll
    for (int off = 16; off > 0; off >>= 1)
        v += __shfl_down_sync(0xFFFFFFFFu, v, off);
    __shared__ int ws[8];
    if ((threadIdx.x & 31) == 0) ws[threadIdx.x >> 5] = v;
    __syncthreads();
    if (threadIdx.x < 8) {
        int s = ws[threadIdx.x];
#pragma unroll
        for (int off = 4; off > 0; off >>= 1)
            s += __shfl_down_sync(0xFFu, s, off);
        if (threadIdx.x == 0) g_bsum[blockIdx.x] = s;
    }
}

__global__ __launch_bounds__(512) void scan2_kernel() {
    __shared__ int sh[512];
    int tid = threadIdx.x;
    int v = (tid < NSB) ? g_bsum[tid] : 0;
    sh[tid] = v;
    __syncthreads();
#pragma unroll
    for (int off = 1; off < 512; off <<= 1) {
        int u = (tid >= off) ? sh[tid - off] : 0;
        __syncthreads();
        sh[tid] += u;
        __syncthreads();
    }
    if (tid < NSB) g_boff[tid] = sh[tid] - v;  // exclusive
}

__global__ __launch_bounds__(SBLK) void scan3_kernel() {
    __shared__ int sh[SBLK];
    int tid = threadIdx.x;
    int i = blockIdx.x * SBLK + tid;
    int v = (i < NNODES) ? g_counts[i] : 0;
    sh[tid] = v;
    __syncthreads();
#pragma unroll
    for (int off = 1; off < SBLK; off <<= 1) {
        int u = (tid >= off) ? sh[tid - off] : 0;
        __syncthreads();
        sh[tid] += u;
        __syncthreads();
    }
    if (i < NNODES) {
        int pos = g_boff[blockIdx.x] + sh[tid] - v;  // exclusive prefix
        g_rowptr[i] = pos;
        g_cursor[i] = pos;
        if (i == NNODES - 1) g_rowptr[NNODES] = NEDGES;
    }
}

// ---------------- K4: scatter src ids grouped by target -------------------
__global__ void scatter_kernel(const int* __restrict__ src,
                               const int* __restrict__ trg) {
    int e = blockIdx.x * blockDim.x + threadIdx.x;
    if (e >= NEDGES) return;
    int t = __ldg(&trg[e]);
    int s = __ldg(&src[e]);
    int pos = atomicAdd(&g_cursor[t], 1);
    g_psrc[pos] = s;
}

// ---------------- K5: single-pass warp-per-node softmax + aggregation -----
// Unnormalized accumulate Sum(e_i * h_i); divide by Sum(e_i)+EPS at the end.
// (Reference's global-max shift cancels to ~1e-15 relative; skipped.)
__global__ __launch_bounds__(256) void agg_kernel(float* __restrict__ out) {
    __shared__ int   s_src[8][32];
    __shared__ float s_exp[8][32 * 4];

    int gw = (blockIdx.x * 256 + threadIdx.x) >> 5;   // node
    int lane = threadIdx.x & 31;
    int ws = (threadIdx.x >> 5);
    if (gw >= NNODES) return;

    int beg = g_rowptr[gw];
    int end = g_rowptr[gw + 1];
    float4 er = g_er[gw];
    int head = lane >> 3;

    float ax = 0.f, ay = 0.f;
    float4 dp = make_float4(0.f, 0.f, 0.f, 0.f);   // per-lane denom partials
    const float2* h2 = reinterpret_cast<const float2*>(g_h);

    for (int t0 = beg; t0 < end; t0 += 32) {
        int cnt = min(32, end - t0);
        int s = 0;
        float4 e4 = make_float4(0.f, 0.f, 0.f, 0.f);
        if (lane < cnt) {
            s = __ldg(&g_psrc[t0 + lane]);          // sequential coalesced
            float4 l = g_el[s];                     // 16B gather, MLP=32
            float sx = l.x + er.x, sy = l.y + er.y;
            float sz = l.z + er.z, sw = l.w + er.w;
            sx = sx > 0.f ? sx : NEG_SLOPE * sx;
            sy = sy > 0.f ? sy : NEG_SLOPE * sy;
            sz = sz > 0.f ? sz : NEG_SLOPE * sz;
            sw = sw > 0.f ? sw : NEG_SLOPE * sw;
            e4 = make_float4(__expf(sx), __expf(sy), __expf(sz), __expf(sw));
            dp.x += e4.x; dp.y += e4.y; dp.z += e4.z; dp.w += e4.w;
        }
        s_src[ws][lane] = s;
        reinterpret_cast<float4*>(s_exp[ws])[lane] = e4;
        __syncwarp();
#pragma unroll 4
        for (int j = 0; j < cnt; j++) {
            int sj = s_src[ws][j];
            float a = s_exp[ws][j * 4 + head];
            float2 hv = h2[(size_t)sj * 32 + lane]; // coalesced 256B row
            ax = fmaf(hv.x, a, ax);
            ay = fmaf(hv.y, a, ay);
        }
        __syncwarp();
    }

    // reduce denom partials across lanes (per component)
#pragma unroll
    for (int off = 16; off > 0; off >>= 1) {
        dp.x += __shfl_xor_sync(0xFFFFFFFFu, dp.x, off);
        dp.y += __shfl_xor_sync(0xFFFFFFFFu, dp.y, off);
        dp.z += __shfl_xor_sync(0xFFFFFFFFu, dp.z, off);
        dp.w += __shfl_xor_sync(0xFFFFFFFFu, dp.w, off);
    }
    float denom = (head == 0) ? dp.x : (head == 1) ? dp.y
                : (head == 2) ? dp.z : dp.w;
    float rd = 1.0f / (denom + EPS_F);
    reinterpret_cast<float2*>(out)[(size_t)gw * 32 + lane] =
        make_float2(ax * rd, ay * rd);
}

// ---------------- launch ---------------------------------------------------
extern "C" void kernel_launch(void* const* d_in, const int* in_sizes, int n_in,
                              void* d_out, int out_size) {
    const float* feat = (const float*)d_in[0];
    const float* W    = (const float*)d_in[1];
    const float* attL = (const float*)d_in[2];
    const float* attR = (const float*)d_in[3];
    const int*   src  = (const int*)d_in[4];
    const int*   trg  = (const int*)d_in[5];
    float* out = (float*)d_out;

    zero_kernel<<<256, 256>>>();
    gemm_kernel<<<(NNODES + 255) / 256, 256>>>(feat, W, attL, attR);
    count_kernel<<<(NEDGES + 255) / 256, 256>>>(trg);
    scan1_kernel<<<NSB, SBLK>>>();
    scan2_kernel<<<1, 512>>>();
    scan3_kernel<<<NSB, SBLK>>>();
    scatter_kernel<<<(NEDGES + 255) / 256, 256>>>(src, trg);
    agg_kernel<<<(NNODES * 32 + 255) / 256, 256>>>(out);
}

// round 5
// speedup vs baseline: 2.0576x; 1.0415x over previous
#include <cuda_runtime.h>
#include <cuda_fp16.h>
#include <cuda_bf16.h>

#define NNODES 100000
#define NEDGES 1600000
#define INF    128
#define HF     64     // HEADS*OUT_FEATS
#define NEG_SLOPE 0.2f
#define EPS_F  1e-16f

#define SBLK 256
#define NSB  ((NNODES + SBLK - 1) / SBLK)   // 391 scan blocks

typedef unsigned long long u64;

// ---------------- static device scratch (no allocations allowed) ----------
__device__ __half g_hh[NNODES * HF];         // 12.8 MB projected features (fp16)
__device__ float4 g_el[NNODES];              // [N][4] left scores
__device__ float4 g_er[NNODES];              // [N][4] right scores
__device__ int    g_counts[NNODES];
__device__ int    g_cursor[NNODES];
__device__ int    g_rowptr[NNODES + 1];
__device__ int    g_psrc[NEDGES];            // src ids grouped by target
__device__ int    g_bsum[NSB];               // per-block count sums
__device__ int    g_boff[NSB];               // exclusive scan of g_bsum

// ---------------- zero counts ---------------------------------------------
__global__ void zero_kernel() {
    int i = blockIdx.x * blockDim.x + threadIdx.x;
    int stride = gridDim.x * blockDim.x;
    for (int j = i; j < NNODES; j += stride) g_counts[j] = 0;
}

// ---------------- packed f32x2 helpers (sm_103a FFMA2) --------------------
__device__ __forceinline__ u64 ffma2(u64 a, u64 b, u64 c) {
    u64 d;
    asm("fma.rn.f32x2 %0, %1, %2, %3;" : "=l"(d) : "l"(a), "l"(b), "l"(c));
    return d;
}
__device__ __forceinline__ u64 bcast2(float x) {
    u64 d;
    unsigned u = __float_as_uint(x);
    asm("mov.b64 %0, {%1, %1};" : "=l"(d) : "r"(u));
    return d;
}
__device__ __forceinline__ void unpack2(u64 v, float& lo, float& hi) {
    unsigned a, b;
    asm("mov.b64 {%0, %1}, %2;" : "=r"(a), "=r"(b) : "l"(v));
    lo = __uint_as_float(a);
    hi = __uint_as_float(b);
}

// ---------------- K1: h = feat @ W (FFMA2), fused el/er epilogue ----------
// 2 nodes per thread: shared-W loads amortized over both accumulators.
__device__ __forceinline__ void gemm_epilogue(int node, const u64* acc,
                                              const float* sAL,
                                              const float* sAR) {
    __half2* hrow = reinterpret_cast<__half2*>(g_hh) + (size_t)node * 32;
    float el[4] = {0.f, 0.f, 0.f, 0.f};
    float er[4] = {0.f, 0.f, 0.f, 0.f};
#pragma unroll
    for (int j = 0; j < 32; j++) {
        float lo, hi;
        unpack2(acc[j], lo, hi);
        hrow[j] = __floats2half2_rn(lo, hi);
        int hd = j >> 3;              // 8 pairs per head
        int j0 = j * 2;
        el[hd] = fmaf(lo, sAL[j0], fmaf(hi, sAL[j0 + 1], el[hd]));
        er[hd] = fmaf(lo, sAR[j0], fmaf(hi, sAR[j0 + 1], er[hd]));
    }
    g_el[node] = make_float4(el[0], el[1], el[2], el[3]);
    g_er[node] = make_float4(er[0], er[1], er[2], er[3]);
}

__global__ __launch_bounds__(256) void gemm_kernel(
    const float* __restrict__ feat, const float* __restrict__ W,
    const float* __restrict__ attL, const float* __restrict__ attR) {
    __shared__ u64  sW2[INF * HF / 2];     // 32 KB: W rows as f32 pairs
    __shared__ float sAL[HF], sAR[HF];
    {
        const float2* ws = reinterpret_cast<const float2*>(W);
        float2* sd = reinterpret_cast<float2*>(sW2);
        for (int i = threadIdx.x; i < INF * HF / 2; i += 256) sd[i] = ws[i];
        if (threadIdx.x < HF) {
            sAL[threadIdx.x] = attL[threadIdx.x];
            sAR[threadIdx.x] = attR[threadIdx.x];
        }
    }
    __syncthreads();

    int n0 = blockIdx.x * 512 + threadIdx.x;
    int n1 = n0 + 256;
    bool v0 = n0 < NNODES, v1 = n1 < NNODES;

    u64 acc0[32], acc1[32];
#pragma unroll
    for (int j = 0; j < 32; j++) { acc0[j] = 0ull; acc1[j] = 0ull; }

    const float4* f0 = reinterpret_cast<const float4*>(feat + (size_t)n0 * INF);
    const float4* f1 = reinterpret_cast<const float4*>(feat + (size_t)n1 * INF);
    const float4 z4 = make_float4(0.f, 0.f, 0.f, 0.f);

    for (int k0 = 0; k0 < 32; k0++) {
        float4 a0 = v0 ? f0[k0] : z4;
        float4 a1 = v1 ? f1[k0] : z4;
#pragma unroll
        for (int sub = 0; sub < 4; sub++) {
            float s0 = sub == 0 ? a0.x : sub == 1 ? a0.y : sub == 2 ? a0.z : a0.w;
            float s1 = sub == 0 ? a1.x : sub == 1 ? a1.y : sub == 2 ? a1.z : a1.w;
            u64 aa0 = bcast2(s0);
            u64 aa1 = bcast2(s1);
            const u64* wr = sW2 + (k0 * 4 + sub) * 32;
#pragma unroll
            for (int j = 0; j < 32; j++) {
                u64 w = wr[j];
                acc0[j] = ffma2(aa0, w, acc0[j]);
                acc1[j] = ffma2(aa1, w, acc1[j]);
            }
        }
    }

    if (v0) gemm_epilogue(n0, acc0, sAL, sAR);
    if (v1) gemm_epilogue(n1, acc1, sAL, sAR);
}

// ---------------- K2: target-degree histogram -----------------------------
__global__ void count_kernel(const int* __restrict__ trg) {
    int e = blockIdx.x * blockDim.x + threadIdx.x;
    if (e >= NEDGES) return;
    atomicAdd(&g_counts[__ldg(&trg[e])], 1);
}

// ---------------- K3: 3-phase parallel exclusive scan of counts -----------
__global__ __launch_bounds__(SBLK) void scan1_kernel() {
    int i = blockIdx.x * SBLK + threadIdx.x;
    int v = (i < NNODES) ? g_counts[i] : 0;
#pragma unroll
    for (int off = 16; off > 0; off >>= 1)
        v += __shfl_down_sync(0xFFFFFFFFu, v, off);
    __shared__ int ws[8];
    if ((threadIdx.x & 31) == 0) ws[threadIdx.x >> 5] = v;
    __syncthreads();
    if (threadIdx.x < 8) {
        int s = ws[threadIdx.x];
#pragma unroll
        for (int off = 4; off > 0; off >>= 1)
            s += __shfl_down_sync(0xFFu, s, off);
        if (threadIdx.x == 0) g_bsum[blockIdx.x] = s;
    }
}

__global__ __launch_bounds__(512) void scan2_kernel() {
    __shared__ int sh[512];
    int tid = threadIdx.x;
    int v = (tid < NSB) ? g_bsum[tid] : 0;
    sh[tid] = v;
    __syncthreads();
#pragma unroll
    for (int off = 1; off < 512; off <<= 1) {
        int u = (tid >= off) ? sh[tid - off] : 0;
        __syncthreads();
        sh[tid] += u;
        __syncthreads();
    }
    if (tid < NSB) g_boff[tid] = sh[tid] - v;  // exclusive
}

__global__ __launch_bounds__(SBLK) void scan3_kernel() {
    __shared__ int sh[SBLK];
    int tid = threadIdx.x;
    int i = blockIdx.x * SBLK + tid;
    int v = (i < NNODES) ? g_counts[i] : 0;
    sh[tid] = v;
    __syncthreads();
#pragma unroll
    for (int off = 1; off < SBLK; off <<= 1) {
        int u = (tid >= off) ? sh[tid - off] : 0;
        __syncthreads();
        sh[tid] += u;
        __syncthreads();
    }
    if (i < NNODES) {
        int pos = g_boff[blockIdx.x] + sh[tid] - v;  // exclusive prefix
        g_rowptr[i] = pos;
        g_cursor[i] = pos;
        if (i == NNODES - 1) g_rowptr[NNODES] = NEDGES;
    }
}

// ---------------- K4: scatter src ids grouped by target -------------------
__global__ void scatter_kernel(const int* __restrict__ src,
                               const int* __restrict__ trg) {
    int e = blockIdx.x * blockDim.x + threadIdx.x;
    if (e >= NEDGES) return;
    int t = __ldg(&trg[e]);
    int s = __ldg(&src[e]);
    int pos = atomicAdd(&g_cursor[t], 1);
    g_psrc[pos] = s;
}

// ---------------- K5: single-pass warp-per-node softmax + aggregation -----
// Unnormalized accumulate Sum(e_i * h_i); divide by Sum(e_i)+EPS at the end.
// (Reference's global-max shift cancels to ~1e-15 relative; skipped.)
__global__ __launch_bounds__(256) void agg_kernel(float* __restrict__ out) {
    __shared__ int   s_src[8][32];
    __shared__ float s_exp[8][32 * 4];

    int gw = (blockIdx.x * 256 + threadIdx.x) >> 5;   // node
    int lane = threadIdx.x & 31;
    int ws = (threadIdx.x >> 5);
    if (gw >= NNODES) return;

    int beg = g_rowptr[gw];
    int end = g_rowptr[gw + 1];
    float4 er = g_er[gw];
    int head = lane >> 3;

    float ax = 0.f, ay = 0.f;
    float4 dp = make_float4(0.f, 0.f, 0.f, 0.f);   // per-lane denom partials
    const __half2* h2p = reinterpret_cast<const __half2*>(g_hh);

    for (int t0 = beg; t0 < end; t0 += 32) {
        int cnt = min(32, end - t0);
        int s = 0;
        float4 e4 = make_float4(0.f, 0.f, 0.f, 0.f);
        if (lane < cnt) {
            s = __ldg(&g_psrc[t0 + lane]);          // sequential coalesced
            float4 l = g_el[s];                     // 16B gather, L2-resident
            float sx = l.x + er.x, sy = l.y + er.y;
            float sz = l.z + er.z, sw = l.w + er.w;
            sx = sx > 0.f ? sx : NEG_SLOPE * sx;
            sy = sy > 0.f ? sy : NEG_SLOPE * sy;
            sz = sz > 0.f ? sz : NEG_SLOPE * sz;
            sw = sw > 0.f ? sw : NEG_SLOPE * sw;
            e4 = make_float4(__expf(sx), __expf(sy), __expf(sz), __expf(sw));
            dp.x += e4.x; dp.y += e4.y; dp.z += e4.z; dp.w += e4.w;
        }
        s_src[ws][lane] = s;
        reinterpret_cast<float4*>(s_exp[ws])[lane] = e4;
        __syncwarp();
#pragma unroll 4
        for (int j = 0; j < cnt; j++) {
            int sj = s_src[ws][j];
            float a = s_exp[ws][j * 4 + head];
            __half2 hv = h2p[(size_t)sj * 32 + lane]; // coalesced 128B row
            float2 f = __half22float2(hv);
            ax = fmaf(f.x, a, ax);
            ay = fmaf(f.y, a, ay);
        }
        __syncwarp();
    }

    // reduce denom partials across lanes (per component)
#pragma unroll
    for (int off = 16; off > 0; off >>= 1) {
        dp.x += __shfl_xor_sync(0xFFFFFFFFu, dp.x, off);
        dp.y += __shfl_xor_sync(0xFFFFFFFFu, dp.y, off);
        dp.z += __shfl_xor_sync(0xFFFFFFFFu, dp.z, off);
        dp.w += __shfl_xor_sync(0xFFFFFFFFu, dp.w, off);
    }
    float denom = (head == 0) ? dp.x : (head == 1) ? dp.y
                : (head == 2) ? dp.z : dp.w;
    float rd = 1.0f / (denom + EPS_F);
    reinterpret_cast<float2*>(out)[(size_t)gw * 32 + lane] =
        make_float2(ax * rd, ay * rd);
}

// ---------------- launch ---------------------------------------------------
extern "C" void kernel_launch(void* const* d_in, const int* in_sizes, int n_in,
                              void* d_out, int out_size) {
    const float* feat = (const float*)d_in[0];
    const float* W    = (const float*)d_in[1];
    const float* attL = (const float*)d_in[2];
    const float* attR = (const float*)d_in[3];
    const int*   src  = (const int*)d_in[4];
    const int*   trg  = (const int*)d_in[5];
    float* out = (float*)d_out;

    zero_kernel<<<256, 256>>>();
    gemm_kernel<<<(NNODES + 511) / 512, 256>>>(feat, W, attL, attR);
    count_kernel<<<(NEDGES + 255) / 256, 256>>>(trg);
    scan1_kernel<<<NSB, SBLK>>>();
    scan2_kernel<<<1, 512>>>();
    scan3_kernel<<<NSB, SBLK>>>();
    scatter_kernel<<<(NEDGES + 255) / 256, 256>>>(src, trg);
    agg_kernel<<<(NNODES * 32 + 255) / 256, 256>>>(out);
}

// round 6
// speedup vs baseline: 2.4739x; 1.2023x over previous
#include <cuda_runtime.h>
#include <cuda_fp16.h>
#include <cuda_bf16.h>

#define NNODES 100000
#define NEDGES 1600000
#define INF    128
#define HF     64     // HEADS*OUT_FEATS
#define NEG_SLOPE 0.2f
#define EPS_F  1e-16f

#define GB_NODES 256                         // nodes per gemm block
#define NGB ((NNODES + GB_NODES - 1) / GB_NODES)   // 391 gemm blocks
#define SBLK 256
#define NSB  ((NNODES + SBLK - 1) / SBLK)    // 391 scan blocks

typedef unsigned long long u64;

// ---------------- static device scratch (no allocations allowed) ----------
__device__ __half g_hh[NNODES * HF];         // 12.8 MB projected features (fp16)
__device__ float4 g_el[NNODES];              // [N][4] left scores
__device__ float4 g_er[NNODES];              // [N][4] right scores
__device__ int    g_counts[NNODES];
__device__ int    g_cursor[NNODES];
__device__ int    g_rowptr[NNODES + 1];
__device__ int    g_psrc[NEDGES];            // src ids grouped by target
__device__ u64    g_state[NSB];              // lookback: (sum<<2)|{0,1,2}

// ---------------- zero counts + lookback state ----------------------------
__global__ void zero_kernel() {
    int i = blockIdx.x * blockDim.x + threadIdx.x;
    int stride = gridDim.x * blockDim.x;
    for (int j = i; j < NNODES; j += stride) g_counts[j] = 0;
    for (int j = i; j < NSB; j += stride)    g_state[j] = 0ull;
}

// ---------------- packed f32x2 helpers (sm_103a FFMA2) --------------------
__device__ __forceinline__ u64 ffma2(u64 a, u64 b, u64 c) {
    u64 d;
    asm("fma.rn.f32x2 %0, %1, %2, %3;" : "=l"(d) : "l"(a), "l"(b), "l"(c));
    return d;
}
__device__ __forceinline__ u64 bcast2(float x) {
    u64 d;
    unsigned u = __float_as_uint(x);
    asm("mov.b64 %0, {%1, %1};" : "=l"(d) : "r"(u));
    return d;
}
__device__ __forceinline__ void unpack2(u64 v, float& lo, float& hi) {
    unsigned a, b;
    asm("mov.b64 {%0, %1}, %2;" : "=r"(a), "=r"(b) : "l"(v));
    lo = __uint_as_float(a);
    hi = __uint_as_float(b);
}

// ---------------- K1: h = feat @ W (FFMA2), tiled --------------------------
// Block: 128 threads, 256 nodes. Thread (g = tid&31, q = tid>>5) computes
// 8 nodes {base+g+32i} x 16 outputs (head q). W broadcast from smem,
// feat staged per-block in smem -> ~96B smem/thread/k, fma-bound.
__global__ __launch_bounds__(128, 2) void gemm_kernel(
    const float* __restrict__ feat, const float* __restrict__ W,
    const float* __restrict__ attL, const float* __restrict__ attR) {
    __shared__ u64   sW2[INF * 32];          // 32 KB: rows of 64 f32 as 32 u64
    __shared__ float sF[8][GB_NODES];        // 8 KB: feat chunk [k][node]
    __shared__ float sAL[HF], sAR[HF];

    {
        const float2* ws = reinterpret_cast<const float2*>(W);
        float2* sd = reinterpret_cast<float2*>(sW2);
        for (int i = threadIdx.x; i < INF * 32; i += 128) sd[i] = ws[i];
        if (threadIdx.x < HF) {
            sAL[threadIdx.x] = attL[threadIdx.x];
            sAR[threadIdx.x] = attR[threadIdx.x];
        }
    }

    int tid = threadIdx.x;
    int g = tid & 31, q = tid >> 5;
    int base = blockIdx.x * GB_NODES;

    u64 acc[64];
#pragma unroll
    for (int j = 0; j < 64; j++) acc[j] = 0ull;

    int ln0 = base + 2 * tid;                // loader nodes
    int ln1 = ln0 + 1;
    const float4 z4 = make_float4(0.f, 0.f, 0.f, 0.f);
    __syncthreads();

    for (int kc = 0; kc < 16; kc++) {
        int ks = kc * 8;
        float4 A0 = z4, A1 = z4, B0 = z4, B1 = z4;
        if (ln0 < NNODES) {
            const float4* p = reinterpret_cast<const float4*>(feat + (size_t)ln0 * INF + ks);
            A0 = p[0]; A1 = p[1];
        }
        if (ln1 < NNODES) {
            const float4* p = reinterpret_cast<const float4*>(feat + (size_t)ln1 * INF + ks);
            B0 = p[0]; B1 = p[1];
        }
        __syncthreads();   // protect sF from previous iteration's readers
        float2* row;
        row = reinterpret_cast<float2*>(&sF[0][2 * tid]); *row = make_float2(A0.x, B0.x);
        row = reinterpret_cast<float2*>(&sF[1][2 * tid]); *row = make_float2(A0.y, B0.y);
        row = reinterpret_cast<float2*>(&sF[2][2 * tid]); *row = make_float2(A0.z, B0.z);
        row = reinterpret_cast<float2*>(&sF[3][2 * tid]); *row = make_float2(A0.w, B0.w);
        row = reinterpret_cast<float2*>(&sF[4][2 * tid]); *row = make_float2(A1.x, B1.x);
        row = reinterpret_cast<float2*>(&sF[5][2 * tid]); *row = make_float2(A1.y, B1.y);
        row = reinterpret_cast<float2*>(&sF[6][2 * tid]); *row = make_float2(A1.z, B1.z);
        row = reinterpret_cast<float2*>(&sF[7][2 * tid]); *row = make_float2(A1.w, B1.w);
        __syncthreads();

#pragma unroll
        for (int k = 0; k < 8; k++) {
            const u64* wr = sW2 + (size_t)(ks + k) * 32 + q * 8;
            u64 w0 = wr[0], w1 = wr[1], w2 = wr[2], w3 = wr[3];
            u64 w4 = wr[4], w5 = wr[5], w6 = wr[6], w7 = wr[7];
#pragma unroll
            for (int i = 0; i < 8; i++) {
                u64 ai = bcast2(sF[k][g + 32 * i]);
                u64* a = acc + i * 8;
                a[0] = ffma2(ai, w0, a[0]);
                a[1] = ffma2(ai, w1, a[1]);
                a[2] = ffma2(ai, w2, a[2]);
                a[3] = ffma2(ai, w3, a[3]);
                a[4] = ffma2(ai, w4, a[4]);
                a[5] = ffma2(ai, w5, a[5]);
                a[6] = ffma2(ai, w6, a[6]);
                a[7] = ffma2(ai, w7, a[7]);
            }
        }
    }

    // epilogue: store h (fp16) + per-head el/er (no cross-thread reduction)
#pragma unroll
    for (int i = 0; i < 8; i++) {
        int n = base + g + 32 * i;
        if (n >= NNODES) continue;
        __half2* hr = reinterpret_cast<__half2*>(g_hh + (size_t)n * HF) + q * 8;
        float elv = 0.f, erv = 0.f;
#pragma unroll
        for (int j = 0; j < 8; j++) {
            float lo, hi;
            unpack2(acc[i * 8 + j], lo, hi);
            hr[j] = __floats2half2_rn(lo, hi);
            int j0 = q * 16 + 2 * j;
            elv = fmaf(lo, sAL[j0], fmaf(hi, sAL[j0 + 1], elv));
            erv = fmaf(lo, sAR[j0], fmaf(hi, sAR[j0 + 1], erv));
        }
        reinterpret_cast<float*>(g_el)[n * 4 + q] = elv;
        reinterpret_cast<float*>(g_er)[n * 4 + q] = erv;
    }
}

// ---------------- K2: target-degree histogram (4 edges/thread) ------------
__global__ void count_kernel(const int* __restrict__ trg) {
    int e4 = blockIdx.x * blockDim.x + threadIdx.x;
    if (e4 >= NEDGES / 4) return;
    int4 t = reinterpret_cast<const int4*>(trg)[e4];
    atomicAdd(&g_counts[t.x], 1);
    atomicAdd(&g_counts[t.y], 1);
    atomicAdd(&g_counts[t.z], 1);
    atomicAdd(&g_counts[t.w], 1);
}

// ---------------- K3: single-kernel decoupled-lookback exclusive scan -----
__global__ __launch_bounds__(SBLK) void scan_kernel() {
    int b = blockIdx.x, tid = threadIdx.x;
    int lane = tid & 31, wid = tid >> 5;
    int i = b * SBLK + tid;
    int v = (i < NNODES) ? g_counts[i] : 0;

    // inclusive warp scan
    int x = v;
#pragma unroll
    for (int off = 1; off < 32; off <<= 1) {
        int u = __shfl_up_sync(0xFFFFFFFFu, x, off);
        if (lane >= off) x += u;
    }
    __shared__ int wsum[8], woff[8];
    __shared__ int s_prev;
    if (lane == 31) wsum[wid] = x;
    __syncthreads();
    if (tid < 8) {
        int t = wsum[tid];
        int s = t;
#pragma unroll
        for (int off = 1; off < 8; off <<= 1) {
            int u = __shfl_up_sync(0xFFu, s, off);
            if (tid >= off) s += u;
        }
        woff[tid] = s - t;                    // exclusive warp offset
        if (tid == 7) {
            int total = s;                    // block sum
            long long prev = 0;
            if (b == 0) {
                atomicExch(&g_state[0], ((u64)total << 2) | 2ull);
            } else {
                atomicExch(&g_state[b], ((u64)total << 2) | 1ull);
                int look = b - 1;
                while (true) {
                    u64 st = atomicAdd(&g_state[look], 0ull);
                    u64 fl = st & 3ull;
                    if (fl == 0ull) { __nanosleep(40); continue; }
                    prev += (long long)(st >> 2);
                    if (fl == 2ull) break;
                    look--;
                }
                atomicExch(&g_state[b], ((u64)(prev + total) << 2) | 2ull);
            }
            s_prev = (int)prev;
        }
    }
    __syncthreads();
    if (i < NNODES) {
        int pos = s_prev + woff[wid] + x - v;  // global exclusive prefix
        g_rowptr[i] = pos;
        g_cursor[i] = pos;
        if (i == NNODES - 1) g_rowptr[NNODES] = NEDGES;
    }
}

// ---------------- K4: scatter src ids grouped by target -------------------
__global__ void scatter_kernel(const int* __restrict__ src,
                               const int* __restrict__ trg) {
    int e4 = blockIdx.x * blockDim.x + threadIdx.x;
    if (e4 >= NEDGES / 4) return;
    int4 t = reinterpret_cast<const int4*>(trg)[e4];
    int4 s = reinterpret_cast<const int4*>(src)[e4];
    g_psrc[atomicAdd(&g_cursor[t.x], 1)] = s.x;
    g_psrc[atomicAdd(&g_cursor[t.y], 1)] = s.y;
    g_psrc[atomicAdd(&g_cursor[t.z], 1)] = s.z;
    g_psrc[atomicAdd(&g_cursor[t.w], 1)] = s.w;
}

// ---------------- K5: single-pass warp-per-node softmax + aggregation -----
// Unnormalized accumulate Sum(e_i * h_i); divide by Sum(e_i)+EPS at the end.
// (Reference's global-max shift cancels to ~1e-15 relative; skipped.)
__global__ __launch_bounds__(256) void agg_kernel(float* __restrict__ out) {
    __shared__ int   s_src[8][32];
    __shared__ float s_exp[8][32 * 4];

    int gw = (blockIdx.x * 256 + threadIdx.x) >> 5;   // node
    int lane = threadIdx.x & 31;
    int ws = (threadIdx.x >> 5);
    if (gw >= NNODES) return;

    int beg = g_rowptr[gw];
    int end = g_rowptr[gw + 1];
    float4 er = g_er[gw];
    int head = lane >> 3;

    float ax = 0.f, ay = 0.f;
    float4 dp = make_float4(0.f, 0.f, 0.f, 0.f);   // per-lane denom partials
    const __half2* h2p = reinterpret_cast<const __half2*>(g_hh);

    for (int t0 = beg; t0 < end; t0 += 32) {
        int cnt = min(32, end - t0);
        int s = 0;
        float4 e4 = make_float4(0.f, 0.f, 0.f, 0.f);
        if (lane < cnt) {
            s = __ldg(&g_psrc[t0 + lane]);          // sequential coalesced
            float4 l = g_el[s];                     // 16B gather, L2-resident
            float sx = l.x + er.x, sy = l.y + er.y;
            float sz = l.z + er.z, sw = l.w + er.w;
            sx = sx > 0.f ? sx : NEG_SLOPE * sx;
            sy = sy > 0.f ? sy : NEG_SLOPE * sy;
            sz = sz > 0.f ? sz : NEG_SLOPE * sz;
            sw = sw > 0.f ? sw : NEG_SLOPE * sw;
            e4 = make_float4(__expf(sx), __expf(sy), __expf(sz), __expf(sw));
            dp.x += e4.x; dp.y += e4.y; dp.z += e4.z; dp.w += e4.w;
        }
        s_src[ws][lane] = s;
        reinterpret_cast<float4*>(s_exp[ws])[lane] = e4;
        __syncwarp();
#pragma unroll 4
        for (int j = 0; j < cnt; j++) {
            int sj = s_src[ws][j];
            float a = s_exp[ws][j * 4 + head];
            __half2 hv = h2p[(size_t)sj * 32 + lane]; // coalesced 128B row
            float2 f = __half22float2(hv);
            ax = fmaf(f.x, a, ax);
            ay = fmaf(f.y, a, ay);
        }
        __syncwarp();
    }

#pragma unroll
    for (int off = 16; off > 0; off >>= 1) {
        dp.x += __shfl_xor_sync(0xFFFFFFFFu, dp.x, off);
        dp.y += __shfl_xor_sync(0xFFFFFFFFu, dp.y, off);
        dp.z += __shfl_xor_sync(0xFFFFFFFFu, dp.z, off);
        dp.w += __shfl_xor_sync(0xFFFFFFFFu, dp.w, off);
    }
    float denom = (head == 0) ? dp.x : (head == 1) ? dp.y
                : (head == 2) ? dp.z : dp.w;
    float rd = 1.0f / (denom + EPS_F);
    reinterpret_cast<float2*>(out)[(size_t)gw * 32 + lane] =
        make_float2(ax * rd, ay * rd);
}

// ---------------- launch ---------------------------------------------------
extern "C" void kernel_launch(void* const* d_in, const int* in_sizes, int n_in,
                              void* d_out, int out_size) {
    const float* feat = (const float*)d_in[0];
    const float* W    = (const float*)d_in[1];
    const float* attL = (const float*)d_in[2];
    const float* attR = (const float*)d_in[3];
    const int*   src  = (const int*)d_in[4];
    const int*   trg  = (const int*)d_in[5];
    float* out = (float*)d_out;

    // side stream + events, created once on the (uncaptured) correctness call
    static cudaStream_t s2 = 0;
    static cudaEvent_t  e0 = 0, e1 = 0;
    static bool ready = false;
    if (!ready) {
        bool ok = (cudaStreamCreateWithFlags(&s2, cudaStreamNonBlocking) == cudaSuccess)
               && (cudaEventCreateWithFlags(&e0, cudaEventDisableTiming) == cudaSuccess)
               && (cudaEventCreateWithFlags(&e1, cudaEventDisableTiming) == cudaSuccess);
        if (!ok) { s2 = 0; e0 = e1 = 0; }
        ready = true;
    }

    bool fork = (s2 != 0);
    if (fork) {
        cudaEventRecord(e0, 0);
        cudaStreamWaitEvent(s2, e0, 0);
    }
    // branch A (side stream): projection GEMM (independent of CSR build)
    gemm_kernel<<<NGB, 128, 0, fork ? s2 : 0>>>(feat, W, attL, attR);
    if (fork) cudaEventRecord(e1, s2);

    // branch B (legacy stream): CSR build
    zero_kernel<<<128, 256>>>();
    count_kernel<<<(NEDGES / 4 + 255) / 256, 256>>>(trg);
    scan_kernel<<<NSB, SBLK>>>();
    scatter_kernel<<<(NEDGES / 4 + 255) / 256, 256>>>(src, trg);

    // join, then aggregate
    if (fork) cudaStreamWaitEvent(0, e1, 0);
    agg_kernel<<<(NNODES * 32 + 255) / 256, 256>>>(out);
}

// round 7
// speedup vs baseline: 2.6621x; 1.0761x over previous
#include <cuda_runtime.h>
#include <cuda_fp16.h>
#include <cuda_bf16.h>

#define NNODES 100000
#define NEDGES 1600000
#define INF    128
#define HF     64     // HEADS*OUT_FEATS
#define NEG_SLOPE 0.2f
#define EPS_F  1e-16f

#define GB_NODES 256                         // nodes per gemm block
#define NGB ((NNODES + GB_NODES - 1) / GB_NODES)   // 391 gemm blocks
#define SBLK 256
#define NSB  ((NNODES + SBLK - 1) / SBLK)    // 391 scan blocks

typedef unsigned long long u64;

// ---------------- static device scratch (no allocations allowed) ----------
// State-recycling invariant: g_counts and g_state are all-zero on entry to
// every kernel_launch call (BSS-zero initially; scan re-zeroes counts after
// consuming them, scatter re-zeroes the lookback states after scan).
__device__ __half g_hh[NNODES * HF];         // 12.8 MB projected features (fp16)
__device__ float4 g_el[NNODES];              // [N][4] left scores
__device__ float4 g_er[NNODES];              // [N][4] right scores
__device__ int    g_counts[NNODES];
__device__ int    g_cursor[NNODES];
__device__ int    g_rowptr[NNODES + 1];
__device__ int    g_psrc[NEDGES];            // src ids grouped by target
__device__ u64    g_state[NSB];              // lookback: (sum<<2)|{0,1,2}

// ---------------- packed f32x2 helpers (sm_103a FFMA2) --------------------
__device__ __forceinline__ u64 ffma2(u64 a, u64 b, u64 c) {
    u64 d;
    asm("fma.rn.f32x2 %0, %1, %2, %3;" : "=l"(d) : "l"(a), "l"(b), "l"(c));
    return d;
}
__device__ __forceinline__ u64 bcast2(float x) {
    u64 d;
    unsigned u = __float_as_uint(x);
    asm("mov.b64 %0, {%1, %1};" : "=l"(d) : "r"(u));
    return d;
}
__device__ __forceinline__ void unpack2(u64 v, float& lo, float& hi) {
    unsigned a, b;
    asm("mov.b64 {%0, %1}, %2;" : "=r"(a), "=r"(b) : "l"(v));
    lo = __uint_as_float(a);
    hi = __uint_as_float(b);
}

// ---------------- K1: h = feat @ W (FFMA2), tiled --------------------------
__global__ __launch_bounds__(128, 2) void gemm_kernel(
    const float* __restrict__ feat, const float* __restrict__ W,
    const float* __restrict__ attL, const float* __restrict__ attR) {
    __shared__ u64   sW2[INF * 32];          // 32 KB: rows of 64 f32 as 32 u64
    __shared__ float sF[8][GB_NODES];        // 8 KB: feat chunk [k][node]
    __shared__ float sAL[HF], sAR[HF];

    {
        const float2* ws = reinterpret_cast<const float2*>(W);
        float2* sd = reinterpret_cast<float2*>(sW2);
        for (int i = threadIdx.x; i < INF * 32; i += 128) sd[i] = ws[i];
        if (threadIdx.x < HF) {
            sAL[threadIdx.x] = attL[threadIdx.x];
            sAR[threadIdx.x] = attR[threadIdx.x];
        }
    }

    int tid = threadIdx.x;
    int g = tid & 31, q = tid >> 5;
    int base = blockIdx.x * GB_NODES;

    u64 acc[64];
#pragma unroll
    for (int j = 0; j < 64; j++) acc[j] = 0ull;

    int ln0 = base + 2 * tid;                // loader nodes
    int ln1 = ln0 + 1;
    const float4 z4 = make_float4(0.f, 0.f, 0.f, 0.f);
    __syncthreads();

    for (int kc = 0; kc < 16; kc++) {
        int ks = kc * 8;
        float4 A0 = z4, A1 = z4, B0 = z4, B1 = z4;
        if (ln0 < NNODES) {
            const float4* p = reinterpret_cast<const float4*>(feat + (size_t)ln0 * INF + ks);
            A0 = p[0]; A1 = p[1];
        }
        if (ln1 < NNODES) {
            const float4* p = reinterpret_cast<const float4*>(feat + (size_t)ln1 * INF + ks);
            B0 = p[0]; B1 = p[1];
        }
        __syncthreads();   // protect sF from previous iteration's readers
        float2* row;
        row = reinterpret_cast<float2*>(&sF[0][2 * tid]); *row = make_float2(A0.x, B0.x);
        row = reinterpret_cast<float2*>(&sF[1][2 * tid]); *row = make_float2(A0.y, B0.y);
        row = reinterpret_cast<float2*>(&sF[2][2 * tid]); *row = make_float2(A0.z, B0.z);
        row = reinterpret_cast<float2*>(&sF[3][2 * tid]); *row = make_float2(A0.w, B0.w);
        row = reinterpret_cast<float2*>(&sF[4][2 * tid]); *row = make_float2(A1.x, B1.x);
        row = reinterpret_cast<float2*>(&sF[5][2 * tid]); *row = make_float2(A1.y, B1.y);
        row = reinterpret_cast<float2*>(&sF[6][2 * tid]); *row = make_float2(A1.z, B1.z);
        row = reinterpret_cast<float2*>(&sF[7][2 * tid]); *row = make_float2(A1.w, B1.w);
        __syncthreads();

#pragma unroll
        for (int k = 0; k < 8; k++) {
            const u64* wr = sW2 + (size_t)(ks + k) * 32 + q * 8;
            u64 w0 = wr[0], w1 = wr[1], w2 = wr[2], w3 = wr[3];
            u64 w4 = wr[4], w5 = wr[5], w6 = wr[6], w7 = wr[7];
#pragma unroll
            for (int i = 0; i < 8; i++) {
                u64 ai = bcast2(sF[k][g + 32 * i]);
                u64* a = acc + i * 8;
                a[0] = ffma2(ai, w0, a[0]);
                a[1] = ffma2(ai, w1, a[1]);
                a[2] = ffma2(ai, w2, a[2]);
                a[3] = ffma2(ai, w3, a[3]);
                a[4] = ffma2(ai, w4, a[4]);
                a[5] = ffma2(ai, w5, a[5]);
                a[6] = ffma2(ai, w6, a[6]);
                a[7] = ffma2(ai, w7, a[7]);
            }
        }
    }

    // epilogue: store h (fp16) + per-head el/er (no cross-thread reduction)
#pragma unroll
    for (int i = 0; i < 8; i++) {
        int n = base + g + 32 * i;
        if (n >= NNODES) continue;
        __half2* hr = reinterpret_cast<__half2*>(g_hh + (size_t)n * HF) + q * 8;
        float elv = 0.f, erv = 0.f;
#pragma unroll
        for (int j = 0; j < 8; j++) {
            float lo, hi;
            unpack2(acc[i * 8 + j], lo, hi);
            hr[j] = __floats2half2_rn(lo, hi);
            int j0 = q * 16 + 2 * j;
            elv = fmaf(lo, sAL[j0], fmaf(hi, sAL[j0 + 1], elv));
            erv = fmaf(lo, sAR[j0], fmaf(hi, sAR[j0 + 1], erv));
        }
        reinterpret_cast<float*>(g_el)[n * 4 + q] = elv;
        reinterpret_cast<float*>(g_er)[n * 4 + q] = erv;
    }
}

// ---------------- K2: target-degree histogram (4 edges/thread) ------------
__global__ void count_kernel(const int* __restrict__ trg) {
    int e4 = blockIdx.x * blockDim.x + threadIdx.x;
    if (e4 >= NEDGES / 4) return;
    int4 t = reinterpret_cast<const int4*>(trg)[e4];
    atomicAdd(&g_counts[t.x], 1);
    atomicAdd(&g_counts[t.y], 1);
    atomicAdd(&g_counts[t.z], 1);
    atomicAdd(&g_counts[t.w], 1);
}

// ---------------- K3: decoupled lookback scan, warp-parallel window -------
// Also re-zeroes g_counts after consuming (state recycling for next call).
__global__ __launch_bounds__(SBLK) void scan_kernel() {
    int b = blockIdx.x, tid = threadIdx.x;
    int lane = tid & 31, wid = tid >> 5;
    int i = b * SBLK + tid;
    int v = (i < NNODES) ? g_counts[i] : 0;

    // inclusive warp scan
    int x = v;
#pragma unroll
    for (int off = 1; off < 32; off <<= 1) {
        int u = __shfl_up_sync(0xFFFFFFFFu, x, off);
        if (lane >= off) x += u;
    }
    __shared__ int wsum[8], woff[8];
    __shared__ int s_prev;
    if (lane == 31) wsum[wid] = x;
    __syncthreads();

    if (tid < 32) {
        // scan the 8 warp sums in lanes 0..7
        int t = (lane < 8) ? wsum[lane] : 0;
        int s = t;
#pragma unroll
        for (int off = 1; off < 8; off <<= 1) {
            int u = __shfl_up_sync(0xFFFFFFFFu, s, off);
            if (lane >= off && lane < 8) s += u;
        }
        if (lane < 8) woff[lane] = s - t;
        int total = __shfl_sync(0xFFFFFFFFu, s, 7);

        if (b == 0) {
            if (lane == 0) {
                atomicExch(&g_state[0], ((u64)total << 2) | 2ull);
                s_prev = 0;
            }
        } else {
            if (lane == 0)
                atomicExch(&g_state[b], ((u64)total << 2) | 1ull);
            long long prev = 0;
            int look = b - 1;
            while (true) {
                int idx = look - lane;               // lane 0 = nearest pred
                u64 st = (idx >= 0) ? atomicAdd(&g_state[idx], 0ull) : 0ull;
                u64 fl = (idx >= 0) ? (st & 3ull) : 2ull;
                unsigned ready = __ballot_sync(0xFFFFFFFFu, fl != 0ull);
                if (ready != 0xFFFFFFFFu) { __nanosleep(20); continue; }
                unsigned pmask = __ballot_sync(0xFFFFFFFFu, fl == 2ull);
                int firstP = __ffs(pmask) - 1;       // -1 if all aggregates
                long long contrib =
                    (firstP < 0 || lane <= firstP) ? (long long)(st >> 2) : 0ll;
#pragma unroll
                for (int off = 16; off > 0; off >>= 1)
                    contrib += __shfl_down_sync(0xFFFFFFFFu, contrib, off);
                contrib = __shfl_sync(0xFFFFFFFFu, contrib, 0);
                prev += contrib;
                if (firstP >= 0) break;
                look -= 32;
            }
            if (lane == 0) {
                atomicExch(&g_state[b], ((u64)(prev + total) << 2) | 2ull);
                s_prev = (int)prev;
            }
        }
    }
    __syncthreads();
    if (i < NNODES) {
        int pos = s_prev + woff[wid] + x - v;  // global exclusive prefix
        g_rowptr[i] = pos;
        g_cursor[i] = pos;
        g_counts[i] = 0;                       // recycle for next call
        if (i == NNODES - 1) g_rowptr[NNODES] = NEDGES;
    }
}

// ---------------- K4: scatter src ids; also recycle lookback state --------
__global__ void scatter_kernel(const int* __restrict__ src,
                               const int* __restrict__ trg) {
    int e4 = blockIdx.x * blockDim.x + threadIdx.x;
    if (e4 < NSB) g_state[e4] = 0ull;          // reset for next call
    if (e4 >= NEDGES / 4) return;
    int4 t = reinterpret_cast<const int4*>(trg)[e4];
    int4 s = reinterpret_cast<const int4*>(src)[e4];
    g_psrc[atomicAdd(&g_cursor[t.x], 1)] = s.x;
    g_psrc[atomicAdd(&g_cursor[t.y], 1)] = s.y;
    g_psrc[atomicAdd(&g_cursor[t.z], 1)] = s.z;
    g_psrc[atomicAdd(&g_cursor[t.w], 1)] = s.w;
}

// ---------------- K5: single-pass warp-per-node softmax + aggregation -----
// Unnormalized accumulate Sum(e_i * h_i); divide by Sum(e_i)+EPS at the end.
// Inner loop: 4 edges x 16B per iteration (jsub = lane>>3, chunk c = lane&7),
// then combine partials across jsub groups with shfl-xor.
__global__ __launch_bounds__(256) void agg_kernel(float* __restrict__ out) {
    __shared__ int   s_src[8][32];
    __shared__ float s_exp[8][32 * 4];

    int gw = (blockIdx.x * 256 + threadIdx.x) >> 5;   // node
    int lane = threadIdx.x & 31;
    int ws = (threadIdx.x >> 5);
    if (gw >= NNODES) return;

    int beg = g_rowptr[gw];
    int end = g_rowptr[gw + 1];
    float4 er = g_er[gw];
    int c = lane & 7;            // feature chunk: halfs [8c, 8c+8)
    int jsub = lane >> 3;        // edge sub-index within group of 4
    int head = c >> 1;           // head of this feature chunk

    float acc[8];
#pragma unroll
    for (int k = 0; k < 8; k++) acc[k] = 0.f;
    float4 dp = make_float4(0.f, 0.f, 0.f, 0.f);   // per-lane denom partials
    const char* hb = reinterpret_cast<const char*>(g_hh);

    for (int t0 = beg; t0 < end; t0 += 32) {
        int cnt = min(32, end - t0);
        int s = 0;
        float4 e4 = make_float4(0.f, 0.f, 0.f, 0.f);
        if (lane < cnt) {
            s = __ldg(&g_psrc[t0 + lane]);          // sequential coalesced
            float4 l = g_el[s];                     // 16B gather, L2-resident
            float sx = l.x + er.x, sy = l.y + er.y;
            float sz = l.z + er.z, sw = l.w + er.w;
            sx = sx > 0.f ? sx : NEG_SLOPE * sx;
            sy = sy > 0.f ? sy : NEG_SLOPE * sy;
            sz = sz > 0.f ? sz : NEG_SLOPE * sz;
            sw = sw > 0.f ? sw : NEG_SLOPE * sw;
            e4 = make_float4(__expf(sx), __expf(sy), __expf(sz), __expf(sw));
            dp.x += e4.x; dp.y += e4.y; dp.z += e4.z; dp.w += e4.w;
        }
        s_src[ws][lane] = s;                        // inactive lanes: 0, a=0
        reinterpret_cast<float4*>(s_exp[ws])[lane] = e4;
        __syncwarp();

        int nIter = (cnt + 3) >> 2;
#pragma unroll 2
        for (int j4 = 0; j4 < nIter; j4++) {
            int j = j4 * 4 + jsub;                  // j <= 31 always
            int sj = s_src[ws][j];
            float a = s_exp[ws][j * 4 + head];
            uint4 hv = *reinterpret_cast<const uint4*>(
                hb + (size_t)sj * 128 + c * 16);
            float2 f0 = __half22float2(*reinterpret_cast<__half2*>(&hv.x));
            float2 f1 = __half22float2(*reinterpret_cast<__half2*>(&hv.y));
            float2 f2 = __half22float2(*reinterpret_cast<__half2*>(&hv.z));
            float2 f3 = __half22float2(*reinterpret_cast<__half2*>(&hv.w));
            acc[0] = fmaf(f0.x, a, acc[0]);
            acc[1] = fmaf(f0.y, a, acc[1]);
            acc[2] = fmaf(f1.x, a, acc[2]);
            acc[3] = fmaf(f1.y, a, acc[3]);
            acc[4] = fmaf(f2.x, a, acc[4]);
            acc[5] = fmaf(f2.y, a, acc[5]);
            acc[6] = fmaf(f3.x, a, acc[6]);
            acc[7] = fmaf(f3.y, a, acc[7]);
        }
        __syncwarp();
    }

    // combine partial sums across the 4 jsub groups (lanes xor 8, 16)
#pragma unroll
    for (int k = 0; k < 8; k++) {
        acc[k] += __shfl_xor_sync(0xFFFFFFFFu, acc[k], 8);
        acc[k] += __shfl_xor_sync(0xFFFFFFFFu, acc[k], 16);
    }

    // reduce denom partials across all lanes
#pragma unroll
    for (int off = 16; off > 0; off >>= 1) {
        dp.x += __shfl_xor_sync(0xFFFFFFFFu, dp.x, off);
        dp.y += __shfl_xor_sync(0xFFFFFFFFu, dp.y, off);
        dp.z += __shfl_xor_sync(0xFFFFFFFFu, dp.z, off);
        dp.w += __shfl_xor_sync(0xFFFFFFFFu, dp.w, off);
    }
    float denom = (head == 0) ? dp.x : (head == 1) ? dp.y
                : (head == 2) ? dp.z : dp.w;
    float rd = 1.0f / (denom + EPS_F);

    if (jsub == 0) {                               // lanes 0..7 write the row
        float4* orow = reinterpret_cast<float4*>(out + (size_t)gw * HF + c * 8);
        orow[0] = make_float4(acc[0] * rd, acc[1] * rd, acc[2] * rd, acc[3] * rd);
        orow[1] = make_float4(acc[4] * rd, acc[5] * rd, acc[6] * rd, acc[7] * rd);
    }
}

// ---------------- launch ---------------------------------------------------
extern "C" void kernel_launch(void* const* d_in, const int* in_sizes, int n_in,
                              void* d_out, int out_size) {
    const float* feat = (const float*)d_in[0];
    const float* W    = (const float*)d_in[1];
    const float* attL = (const float*)d_in[2];
    const float* attR = (const float*)d_in[3];
    const int*   src  = (const int*)d_in[4];
    const int*   trg  = (const int*)d_in[5];
    float* out = (float*)d_out;

    // side stream + events, created once on the (uncaptured) correctness call
    static cudaStream_t s2 = 0;
    static cudaEvent_t  e0 = 0, e1 = 0;
    static bool ready = false;
    if (!ready) {
        bool ok = (cudaStreamCreateWithFlags(&s2, cudaStreamNonBlocking) == cudaSuccess)
               && (cudaEventCreateWithFlags(&e0, cudaEventDisableTiming) == cudaSuccess)
               && (cudaEventCreateWithFlags(&e1, cudaEventDisableTiming) == cudaSuccess);
        if (!ok) { s2 = 0; e0 = e1 = 0; }
        ready = true;
    }

    bool fork = (s2 != 0);
    if (fork) {
        cudaEventRecord(e0, 0);
        cudaStreamWaitEvent(s2, e0, 0);
    }
    // branch A (side stream): projection GEMM (independent of CSR build)
    gemm_kernel<<<NGB, 128, 0, fork ? s2 : 0>>>(feat, W, attL, attR);
    if (fork) cudaEventRecord(e1, s2);

    // branch B (legacy stream): CSR build
    count_kernel<<<(NEDGES / 4 + 255) / 256, 256>>>(trg);
    scan_kernel<<<NSB, SBLK>>>();
    scatter_kernel<<<(NEDGES / 4 + 255) / 256, 256>>>(src, trg);

    // join, then aggregate
    if (fork) cudaStreamWaitEvent(0, e1, 0);
    agg_kernel<<<(NNODES * 32 + 255) / 256, 256>>>(out);
}